// round 1
// baseline (speedup 1.0000x reference)
#include <cuda_runtime.h>
#include <cuda_bf16.h>
#include <cstdint>

#define MSL 256
#define EMB 1024
#define NHID 64
#define NEGF (-1e20f)

// Deterministic scratch: per-position partial dot products. [in/mem][pos][k]
__device__ float g_part[2][MSL][NHID];

// ---------------------------------------------------------------------------
// Kernel A: fused dual GEMV over w1.
// grid = 256 (one block per token position), block = 256 threads.
// Block pos streams w1[pos*1024*64 .. +65536) once, computing partial sums of
//   h_in[k]  += emb[tok_in ][d] * w1[(pos*1024+d)*64+k]
//   h_mem[k] += emb[tok_mem][d] * w1[(pos*1024+d)*64+k]
// Thread t handles k-quad k0=(t&15)*4 and d-stripe j_off=t>>4 (d = d0+j_off).
// w1 float4 address = wrow4[d0*16 + t]  -> perfectly contiguous 4KB per step.
// ---------------------------------------------------------------------------
__global__ __launch_bounds__(256) void gemv_kernel(
    const int* __restrict__ toks_in, int n_toks,
    const int* __restrict__ toks_mem,
    const float* __restrict__ emb,
    const float* __restrict__ w1)
{
    __shared__ float s_in[EMB];
    __shared__ float s_mem[EMB];

    const int pos = blockIdx.x;
    const int t   = threadIdx.x;

    const int tok_in  = (pos < n_toks) ? toks_in[pos] : 0;  // PAD = 0
    const int tok_mem = toks_mem[pos];

    // Cooperative load of the two embedding rows (4KB each) into SMEM.
    const float4* ein  = (const float4*)(emb + (size_t)tok_in  * EMB);
    const float4* emem = (const float4*)(emb + (size_t)tok_mem * EMB);
    ((float4*)s_in)[t]  = ein[t];
    ((float4*)s_mem)[t] = emem[t];
    __syncthreads();

    const float4* wrow4 = (const float4*)(w1 + (size_t)pos * EMB * NHID);
    const int j_off = t >> 4;          // 0..15  (d stripe)
    const int k0    = (t & 15) * 4;    // 0,4,...,60

    float4 ai = make_float4(0.f, 0.f, 0.f, 0.f);
    float4 am = make_float4(0.f, 0.f, 0.f, 0.f);

    #pragma unroll 8
    for (int d0 = 0; d0 < EMB; d0 += 16) {
        float4 w = wrow4[d0 * 16 + t];   // contiguous across the block
        int   d  = d0 + j_off;
        float a  = s_in[d];
        float b  = s_mem[d];
        ai.x += a * w.x; ai.y += a * w.y; ai.z += a * w.z; ai.w += a * w.w;
        am.x += b * w.x; am.y += b * w.y; am.z += b * w.z; am.w += b * w.w;
    }

    // Block reduction over the 16 d-stripes, per k. Reuse s_in/s_mem.
    __syncthreads();
    s_in [j_off * NHID + k0 + 0] = ai.x;
    s_in [j_off * NHID + k0 + 1] = ai.y;
    s_in [j_off * NHID + k0 + 2] = ai.z;
    s_in [j_off * NHID + k0 + 3] = ai.w;
    s_mem[j_off * NHID + k0 + 0] = am.x;
    s_mem[j_off * NHID + k0 + 1] = am.y;
    s_mem[j_off * NHID + k0 + 2] = am.z;
    s_mem[j_off * NHID + k0 + 3] = am.w;
    __syncthreads();

    if (t < NHID) {
        float si = 0.f, sm = 0.f;
        #pragma unroll
        for (int r = 0; r < 16; ++r) {
            si += s_in [r * NHID + t];
            sm += s_mem[r * NHID + t];
        }
        g_part[0][pos][t] = si;
        g_part[1][pos][t] = sm;
    }
}

// ---------------------------------------------------------------------------
// Bitonic sort of 512 u64 keys in shared memory, 256 threads, ascending.
// ---------------------------------------------------------------------------
__device__ __forceinline__ void bitonic_sort_512(unsigned long long* keys)
{
    const int t = threadIdx.x;
    for (int k = 2; k <= 512; k <<= 1) {
        for (int j = k >> 1; j > 0; j >>= 1) {
            __syncthreads();
            int i   = ((t & ~(j - 1)) << 1) | (t & (j - 1));
            int ixj = i | j;
            unsigned long long a = keys[i];
            unsigned long long b = keys[ixj];
            bool up = ((i & k) == 0);
            if ((a > b) == up) { keys[i] = b; keys[ixj] = a; }
        }
    }
    __syncthreads();
}

// ---------------------------------------------------------------------------
// Kernel B: reduce partials -> h (ReLU) -> layer2 + sigmoid -> mask PAD ->
// scatter-max dedup + top-k via two bitonic sorts -> write output.
// 1 block, 256 threads.
// ---------------------------------------------------------------------------
__global__ __launch_bounds__(256) void final_kernel(
    const int* __restrict__ toks_in, int n_toks,
    const int* __restrict__ toks_mem,
    const float* __restrict__ b1,
    const float* __restrict__ w2,
    const float* __restrict__ b2,
    float* __restrict__ out)
{
    __shared__ float h_in[NHID];
    __shared__ float h_mem[NHID];
    __shared__ float sc_in[MSL];
    __shared__ float sc_mem[MSL];
    __shared__ float red[2][4][NHID];
    __shared__ unsigned long long keys[512];

    const int t = threadIdx.x;

    // ---- Phase 1: reduce 256 per-position partials, +b1, ReLU ----
    {
        const int k = t & 63;
        const int q = t >> 6;            // 0..3, each sums 64 positions
        float si = 0.f, sm = 0.f;
        #pragma unroll 4
        for (int b = q * 64; b < q * 64 + 64; ++b) {
            si += g_part[0][b][k];
            sm += g_part[1][b][k];
        }
        red[0][q][k] = si;
        red[1][q][k] = sm;
    }
    __syncthreads();
    if (t < NHID) {
        float a = red[0][0][t] + red[0][1][t] + red[0][2][t] + red[0][3][t] + b1[t];
        float m = red[1][0][t] + red[1][1][t] + red[1][2][t] + red[1][3][t] + b1[t];
        h_in[t]  = fmaxf(a, 0.f);
        h_mem[t] = fmaxf(m, 0.f);
    }
    __syncthreads();

    // ---- Phase 2: second layer + sigmoid (w2 read once, shared) ----
    {
        float si = b2[t];
        float sm = si;
        #pragma unroll 8
        for (int k = 0; k < NHID; ++k) {
            float w = w2[k * MSL + t];   // coalesced over t
            si += h_in[k]  * w;
            sm += h_mem[k] * w;
        }
        sc_in[t]  = 1.f / (1.f + expf(-si));
        sc_mem[t] = 1.f / (1.f + expf(-sm));
    }
    __syncthreads();

    // ---- Phase 3: build keys (token asc, score desc); PAD -> sentinel ----
    {
        int tok_a = (t < n_toks) ? toks_in[t] : 0;
        int tok_b = toks_mem[t];
        unsigned sb_a = __float_as_uint(sc_in[t]);   // positive floats: bits monotonic
        unsigned sb_b = __float_as_uint(sc_mem[t]);
        keys[t] = (tok_a == 0) ? ~0ull
                 : (((unsigned long long)(unsigned)tok_a << 32) | (unsigned)(~sb_a));
        keys[t + 256] = (tok_b == 0) ? ~0ull
                 : (((unsigned long long)(unsigned)tok_b << 32) | (unsigned)(~sb_b));
    }

    // Sort1: groups duplicates; best score first within each token group.
    bitonic_sort_512(keys);

    // ---- Phase 4: dedup (scatter-max): winner = first entry of its token ----
    unsigned long long k_a = keys[t];
    unsigned long long k_b = keys[t + 256];
    unsigned long long p_a = (t == 0) ? ~0ull : keys[t - 1];
    unsigned long long p_b = keys[t + 255];
    bool win_a = (k_a != ~0ull) && (t == 0 || (k_a >> 32) != (p_a >> 32));
    bool win_b = (k_b != ~0ull) && ((k_b >> 32) != (p_b >> 32));
    __syncthreads();

    // key2 = swap halves: (~score_bits)<<32 | token  -> ascending = score desc, token asc
    keys[t]       = win_a ? ((k_a << 32) | (k_a >> 32)) : ~0ull;
    keys[t + 256] = win_b ? ((k_b << 32) | (k_b >> 32)) : ~0ull;

    // Sort2: top-k order.
    bitonic_sort_512(keys);

    // ---- Phase 5: emit first 256 (tokens as float, then scores) ----
    {
        unsigned long long r = keys[t];
        bool present = (r != ~0ull);
        unsigned tok = (unsigned)r;                       // low 32
        float score  = __uint_as_float(~(unsigned)(r >> 32));
        out[t]       = present ? (float)tok : 0.0f;
        out[MSL + t] = present ? score : NEGF;
    }
}

extern "C" void kernel_launch(void* const* d_in, const int* in_sizes, int n_in,
                              void* d_out, int out_size)
{
    const int*   toks_in  = (const int*)  d_in[0];
    const int*   toks_mem = (const int*)  d_in[1];
    const float* emb      = (const float*)d_in[2];
    const float* w1       = (const float*)d_in[3];
    const float* b1       = (const float*)d_in[4];
    const float* w2       = (const float*)d_in[5];
    const float* b2       = (const float*)d_in[6];
    const int n_toks = in_sizes[0];

    gemv_kernel<<<MSL, 256>>>(toks_in, n_toks, toks_mem, emb, w1);
    final_kernel<<<1, 256>>>(toks_in, n_toks, toks_mem, b1, w2, b2, (float*)d_out);
}

// round 2
// speedup vs baseline: 1.1520x; 1.1520x over previous
#include <cuda_runtime.h>
#include <cuda_bf16.h>
#include <cstdint>

#define MSL 256
#define EMB 1024
#define NHID 64
#define NEGF (-1e20f)

// Deterministic scratch: per-position partial dot products. [in/mem][pos][k]
__device__ float g_part[2][MSL][NHID];
// Reduced + ReLU'd hidden vectors. [in/mem][k]
__device__ float g_h[2][NHID];

// ---------------------------------------------------------------------------
// Kernel A: fused dual GEMV over w1.
// grid = 256 (one block per token position), block = 256 threads.
// Streams the block's contiguous 256KB slab of w1 exactly once (coalesced
// float4), computing partials for both the input-token row and memory-token
// row of this position (w1 shared between the two score_net calls).
// ---------------------------------------------------------------------------
__global__ __launch_bounds__(256) void gemv_kernel(
    const int* __restrict__ toks_in, int n_toks,
    const int* __restrict__ toks_mem,
    const float* __restrict__ emb,
    const float* __restrict__ w1)
{
    __shared__ float s_in[EMB];
    __shared__ float s_mem[EMB];

    const int pos = blockIdx.x;
    const int t   = threadIdx.x;

    const int tok_in  = (pos < n_toks) ? toks_in[pos] : 0;  // PAD = 0
    const int tok_mem = toks_mem[pos];

    const float4* ein  = (const float4*)(emb + (size_t)tok_in  * EMB);
    const float4* emem = (const float4*)(emb + (size_t)tok_mem * EMB);
    ((float4*)s_in)[t]  = ein[t];
    ((float4*)s_mem)[t] = emem[t];
    __syncthreads();

    const float4* wrow4 = (const float4*)(w1 + (size_t)pos * EMB * NHID);
    const int j_off = t >> 4;          // 0..15  (d stripe)
    const int k0    = (t & 15) * 4;    // 0,4,...,60

    float4 ai = make_float4(0.f, 0.f, 0.f, 0.f);
    float4 am = make_float4(0.f, 0.f, 0.f, 0.f);

    #pragma unroll 8
    for (int d0 = 0; d0 < EMB; d0 += 16) {
        float4 w = wrow4[d0 * 16 + t];   // contiguous across the block
        int   d  = d0 + j_off;
        float a  = s_in[d];
        float b  = s_mem[d];
        ai.x += a * w.x; ai.y += a * w.y; ai.z += a * w.z; ai.w += a * w.w;
        am.x += b * w.x; am.y += b * w.y; am.z += b * w.z; am.w += b * w.w;
    }

    __syncthreads();
    s_in [j_off * NHID + k0 + 0] = ai.x;
    s_in [j_off * NHID + k0 + 1] = ai.y;
    s_in [j_off * NHID + k0 + 2] = ai.z;
    s_in [j_off * NHID + k0 + 3] = ai.w;
    s_mem[j_off * NHID + k0 + 0] = am.x;
    s_mem[j_off * NHID + k0 + 1] = am.y;
    s_mem[j_off * NHID + k0 + 2] = am.z;
    s_mem[j_off * NHID + k0 + 3] = am.w;
    __syncthreads();

    if (t < NHID) {
        float si = 0.f, sm = 0.f;
        #pragma unroll
        for (int r = 0; r < 16; ++r) {
            si += s_in [r * NHID + t];
            sm += s_mem[r * NHID + t];
        }
        g_part[0][pos][t] = si;
        g_part[1][pos][t] = sm;
    }
}

// ---------------------------------------------------------------------------
// Kernel B: wide reduction of g_part across the 256 positions.
// grid = 128 (one block per (s,k) output), block = 256.
// Plenty of blocks -> L2 latency fully hidden (unlike doing this with 8 warps
// inside the single-block final kernel). Fixed tree -> deterministic.
// ---------------------------------------------------------------------------
__global__ __launch_bounds__(256) void reduce_kernel(
    const float* __restrict__ b1)
{
    __shared__ float warp_sums[8];
    const int s = blockIdx.x >> 6;     // 0..1
    const int k = blockIdx.x & 63;     // 0..63
    const int t = threadIdx.x;

    float v = g_part[s][t][k];

    #pragma unroll
    for (int off = 16; off > 0; off >>= 1)
        v += __shfl_down_sync(0xffffffffu, v, off);
    if ((t & 31) == 0) warp_sums[t >> 5] = v;
    __syncthreads();
    if (t == 0) {
        float sum = 0.f;
        #pragma unroll
        for (int w = 0; w < 8; ++w) sum += warp_sums[w];
        g_h[s][k] = fmaxf(sum + b1[k], 0.f);
    }
}

// ---------------------------------------------------------------------------
// Bitonic sort of 512 u64 keys in shared memory, 256 threads, ascending.
// Sync elision: for j <= 32, thread pairs (i, i|j) with
// i = ((t&~(j-1))<<1)|(t&(j-1)) stay inside warp-private 64-element segments
// [64w, 64w+64), so __syncwarp suffices. Only j >= 64 stages (and the stage
// immediately after one) need a full __syncthreads.
// ---------------------------------------------------------------------------
__device__ __forceinline__ void bitonic_sort_512(unsigned long long* keys)
{
    const int t = threadIdx.x;
    bool prev_cross = true;  // entry data written by all threads
    for (int k = 2; k <= 512; k <<= 1) {
        for (int j = k >> 1; j > 0; j >>= 1) {
            const bool cross = (j >= 64);
            if (cross || prev_cross) __syncthreads();
            else                     __syncwarp();
            prev_cross = cross;
            int i   = ((t & ~(j - 1)) << 1) | (t & (j - 1));
            int ixj = i | j;
            unsigned long long a = keys[i];
            unsigned long long b = keys[ixj];
            bool up = ((i & k) == 0);
            if ((a > b) == up) { keys[i] = b; keys[ixj] = a; }
        }
    }
    __syncthreads();
}

// ---------------------------------------------------------------------------
// Kernel C: layer2 + sigmoid -> mask PAD -> scatter-max dedup + top-k via
// two bitonic sorts -> emit. 1 block, 256 threads.
// ---------------------------------------------------------------------------
__global__ __launch_bounds__(256) void final_kernel(
    const int* __restrict__ toks_in, int n_toks,
    const int* __restrict__ toks_mem,
    const float* __restrict__ w2,
    const float* __restrict__ b2,
    float* __restrict__ out)
{
    __shared__ float h_in[NHID];
    __shared__ float h_mem[NHID];
    __shared__ unsigned long long keys[512];

    const int t = threadIdx.x;

    if (t < NHID)        h_in [t]        = g_h[0][t];
    else if (t < 2*NHID) h_mem[t - NHID] = g_h[1][t - NHID];
    __syncthreads();

    // ---- layer 2 + sigmoid (w2 column shared by both score vectors) ----
    float si, sm;
    {
        si = b2[t];
        sm = si;
        #pragma unroll 16
        for (int k = 0; k < NHID; ++k) {
            float w = w2[k * MSL + t];   // coalesced over t
            si += h_in[k]  * w;
            sm += h_mem[k] * w;
        }
        si = 1.f / (1.f + expf(-si));
        sm = 1.f / (1.f + expf(-sm));
    }

    // ---- build keys (token asc, score desc); PAD -> sentinel ----
    {
        int tok_a = (t < n_toks) ? toks_in[t] : 0;
        int tok_b = toks_mem[t];
        unsigned sb_a = __float_as_uint(si);   // positive floats: bits monotonic
        unsigned sb_b = __float_as_uint(sm);
        keys[t] = (tok_a == 0) ? ~0ull
                 : (((unsigned long long)(unsigned)tok_a << 32) | (unsigned)(~sb_a));
        keys[t + 256] = (tok_b == 0) ? ~0ull
                 : (((unsigned long long)(unsigned)tok_b << 32) | (unsigned)(~sb_b));
    }

    // Sort1: groups duplicates; best score first within each token group.
    bitonic_sort_512(keys);

    // ---- dedup (scatter-max): winner = first entry of its token ----
    unsigned long long k_a = keys[t];
    unsigned long long k_b = keys[t + 256];
    unsigned long long p_a = (t == 0) ? ~0ull : keys[t - 1];
    unsigned long long p_b = keys[t + 255];
    bool win_a = (k_a != ~0ull) && (t == 0 || (k_a >> 32) != (p_a >> 32));
    bool win_b = (k_b != ~0ull) && ((k_b >> 32) != (p_b >> 32));
    __syncthreads();

    // key2 = swap halves: (~score_bits)<<32 | token -> asc = score desc, tok asc
    keys[t]       = win_a ? ((k_a << 32) | (k_a >> 32)) : ~0ull;
    keys[t + 256] = win_b ? ((k_b << 32) | (k_b >> 32)) : ~0ull;

    // Sort2: top-k order.
    bitonic_sort_512(keys);

    // ---- emit first 256 (tokens as float, then scores) ----
    {
        unsigned long long r = keys[t];
        bool present = (r != ~0ull);
        unsigned tok = (unsigned)r;                       // low 32
        float score  = __uint_as_float(~(unsigned)(r >> 32));
        out[t]       = present ? (float)tok : 0.0f;
        out[MSL + t] = present ? score : NEGF;
    }
}

extern "C" void kernel_launch(void* const* d_in, const int* in_sizes, int n_in,
                              void* d_out, int out_size)
{
    const int*   toks_in  = (const int*)  d_in[0];
    const int*   toks_mem = (const int*)  d_in[1];
    const float* emb      = (const float*)d_in[2];
    const float* w1       = (const float*)d_in[3];
    const float* b1       = (const float*)d_in[4];
    const float* w2       = (const float*)d_in[5];
    const float* b2       = (const float*)d_in[6];
    const int n_toks = in_sizes[0];

    gemv_kernel<<<MSL, 256>>>(toks_in, n_toks, toks_mem, emb, w1);
    reduce_kernel<<<128, 256>>>(b1);
    final_kernel<<<1, 256>>>(toks_in, n_toks, toks_mem, w2, b2, (float*)d_out);
}

// round 3
// speedup vs baseline: 1.2322x; 1.0697x over previous
#include <cuda_runtime.h>
#include <cuda_bf16.h>
#include <cstdint>

#define MSL 256
#define EMB 1024
#define NHID 64
#define NSLAB 4
#define DSLAB (EMB / NSLAB)   // 256
#define NEGF (-1e20f)

// Transposed scratch for coalesced reduction: [in/mem][slab][k][pos]
__device__ float g_part[2][NSLAB][NHID][MSL];
// Reduced + ReLU'd hidden vectors. [in/mem][k]
__device__ float g_h[2][NHID];

// ---------------------------------------------------------------------------
// Kernel A: fused dual GEMV over w1, K-split for occupancy.
// grid = 1024 (pos = b>>2, slab = b&3), block = 256 threads.
// Each block streams a contiguous 64KB slab of w1 once (coalesced float4,
// 16 independent loads fully unrolled -> high MLP), computing partials for
// both the input-token and memory-token embedding of this position.
// ---------------------------------------------------------------------------
__global__ __launch_bounds__(256) void gemv_kernel(
    const int* __restrict__ toks_in, int n_toks,
    const int* __restrict__ toks_mem,
    const float* __restrict__ emb,
    const float* __restrict__ w1)
{
    __shared__ float s_in[DSLAB];
    __shared__ float s_mem[DSLAB];
    __shared__ float red_in[16][NHID];
    __shared__ float red_mem[16][NHID];

    const int pos    = blockIdx.x >> 2;
    const int slab   = blockIdx.x & 3;
    const int d_base = slab * DSLAB;
    const int t      = threadIdx.x;

    const int tok_in  = (pos < n_toks) ? toks_in[pos] : 0;  // PAD = 0
    const int tok_mem = toks_mem[pos];

    // Cooperative load of the two 1KB embedding slab segments into SMEM.
    if (t < 64) {
        ((float4*)s_in)[t] =
            ((const float4*)(emb + (size_t)tok_in * EMB + d_base))[t];
    } else if (t < 128) {
        ((float4*)s_mem)[t - 64] =
            ((const float4*)(emb + (size_t)tok_mem * EMB + d_base))[t - 64];
    }
    __syncthreads();

    const float4* wrow4 =
        (const float4*)(w1 + ((size_t)pos * EMB + d_base) * NHID);
    const int j_off = t >> 4;          // 0..15  (d stripe)
    const int k0    = (t & 15) * 4;    // 0,4,...,60

    float4 ai = make_float4(0.f, 0.f, 0.f, 0.f);
    float4 am = make_float4(0.f, 0.f, 0.f, 0.f);

    #pragma unroll
    for (int d0 = 0; d0 < DSLAB; d0 += 16) {
        float4 w = wrow4[d0 * 16 + t];   // contiguous 4KB across the block
        int   d  = d0 + j_off;
        float a  = s_in[d];
        float b  = s_mem[d];
        ai.x += a * w.x; ai.y += a * w.y; ai.z += a * w.z; ai.w += a * w.w;
        am.x += b * w.x; am.y += b * w.y; am.z += b * w.z; am.w += b * w.w;
    }

    red_in [j_off][k0 + 0] = ai.x;
    red_in [j_off][k0 + 1] = ai.y;
    red_in [j_off][k0 + 2] = ai.z;
    red_in [j_off][k0 + 3] = ai.w;
    red_mem[j_off][k0 + 0] = am.x;
    red_mem[j_off][k0 + 1] = am.y;
    red_mem[j_off][k0 + 2] = am.z;
    red_mem[j_off][k0 + 3] = am.w;
    __syncthreads();

    if (t < NHID) {
        float si = 0.f, sm = 0.f;
        #pragma unroll
        for (int r = 0; r < 16; ++r) {
            si += red_in [r][t];
            sm += red_mem[r][t];
        }
        g_part[0][slab][t][pos] = si;
        g_part[1][slab][t][pos] = sm;
    }
}

// ---------------------------------------------------------------------------
// Kernel B: reduce g_part over (slab, pos) -> +b1 -> ReLU -> g_h.
// grid = 128 (one block per (s,k)), block = 256 (one thread per pos).
// Loads are fully coalesced thanks to the [k][pos] scratch layout.
// Fixed tree -> deterministic.
// ---------------------------------------------------------------------------
__global__ __launch_bounds__(256) void reduce_kernel(
    const float* __restrict__ b1)
{
    __shared__ float warp_sums[8];
    const int s = blockIdx.x >> 6;     // 0..1
    const int k = blockIdx.x & 63;     // 0..63
    const int t = threadIdx.x;

    float v = g_part[s][0][k][t] + g_part[s][1][k][t]
            + g_part[s][2][k][t] + g_part[s][3][k][t];

    #pragma unroll
    for (int off = 16; off > 0; off >>= 1)
        v += __shfl_down_sync(0xffffffffu, v, off);
    if ((t & 31) == 0) warp_sums[t >> 5] = v;
    __syncthreads();
    if (t == 0) {
        float sum = 0.f;
        #pragma unroll
        for (int w = 0; w < 8; ++w) sum += warp_sums[w];
        g_h[s][k] = fmaxf(sum + b1[k], 0.f);
    }
}

// ---------------------------------------------------------------------------
// Bitonic sort of 512 u64 keys in shared memory, 256 threads, ascending.
// j <= 32 stages stay inside warp-private 64-element segments -> __syncwarp.
// ---------------------------------------------------------------------------
__device__ __forceinline__ void bitonic_sort_512(unsigned long long* keys)
{
    const int t = threadIdx.x;
    bool prev_cross = true;
    for (int k = 2; k <= 512; k <<= 1) {
        for (int j = k >> 1; j > 0; j >>= 1) {
            const bool cross = (j >= 64);
            if (cross || prev_cross) __syncthreads();
            else                     __syncwarp();
            prev_cross = cross;
            int i   = ((t & ~(j - 1)) << 1) | (t & (j - 1));
            int ixj = i | j;
            unsigned long long a = keys[i];
            unsigned long long b = keys[ixj];
            bool up = ((i & k) == 0);
            if ((a > b) == up) { keys[i] = b; keys[ixj] = a; }
        }
    }
    __syncthreads();
}

// ---------------------------------------------------------------------------
// Kernel C: layer2 + sigmoid -> mask PAD -> scatter-max dedup + top-k via
// two bitonic sorts -> emit. 1 block, 256 threads.
// ---------------------------------------------------------------------------
__global__ __launch_bounds__(256) void final_kernel(
    const int* __restrict__ toks_in, int n_toks,
    const int* __restrict__ toks_mem,
    const float* __restrict__ w2,
    const float* __restrict__ b2,
    float* __restrict__ out)
{
    __shared__ float h_in[NHID];
    __shared__ float h_mem[NHID];
    __shared__ unsigned long long keys[512];

    const int t = threadIdx.x;

    if (t < NHID)        h_in [t]        = g_h[0][t];
    else if (t < 2*NHID) h_mem[t - NHID] = g_h[1][t - NHID];
    __syncthreads();

    // ---- layer 2 + sigmoid (w2 column shared by both score vectors) ----
    float si, sm;
    {
        si = b2[t];
        sm = si;
        #pragma unroll 16
        for (int k = 0; k < NHID; ++k) {
            float w = w2[k * MSL + t];   // coalesced over t
            si += h_in[k]  * w;
            sm += h_mem[k] * w;
        }
        si = 1.f / (1.f + expf(-si));
        sm = 1.f / (1.f + expf(-sm));
    }

    // ---- build keys (token asc, score desc); PAD -> sentinel ----
    {
        int tok_a = (t < n_toks) ? toks_in[t] : 0;
        int tok_b = toks_mem[t];
        unsigned sb_a = __float_as_uint(si);   // positive floats: bits monotonic
        unsigned sb_b = __float_as_uint(sm);
        keys[t] = (tok_a == 0) ? ~0ull
                 : (((unsigned long long)(unsigned)tok_a << 32) | (unsigned)(~sb_a));
        keys[t + 256] = (tok_b == 0) ? ~0ull
                 : (((unsigned long long)(unsigned)tok_b << 32) | (unsigned)(~sb_b));
    }

    // Sort1: groups duplicates; best score first within each token group.
    bitonic_sort_512(keys);

    // ---- dedup (scatter-max): winner = first entry of its token ----
    unsigned long long k_a = keys[t];
    unsigned long long k_b = keys[t + 256];
    unsigned long long p_a = (t == 0) ? ~0ull : keys[t - 1];
    unsigned long long p_b = keys[t + 255];
    bool win_a = (k_a != ~0ull) && (t == 0 || (k_a >> 32) != (p_a >> 32));
    bool win_b = (k_b != ~0ull) && ((k_b >> 32) != (p_b >> 32));
    __syncthreads();

    // key2 = swap halves: (~score_bits)<<32 | token -> asc = score desc, tok asc
    keys[t]       = win_a ? ((k_a << 32) | (k_a >> 32)) : ~0ull;
    keys[t + 256] = win_b ? ((k_b << 32) | (k_b >> 32)) : ~0ull;

    // Sort2: top-k order.
    bitonic_sort_512(keys);

    // ---- emit first 256 (tokens as float, then scores) ----
    {
        unsigned long long r = keys[t];
        bool present = (r != ~0ull);
        unsigned tok = (unsigned)r;                       // low 32
        float score  = __uint_as_float(~(unsigned)(r >> 32));
        out[t]       = present ? (float)tok : 0.0f;
        out[MSL + t] = present ? score : NEGF;
    }
}

extern "C" void kernel_launch(void* const* d_in, const int* in_sizes, int n_in,
                              void* d_out, int out_size)
{
    const int*   toks_in  = (const int*)  d_in[0];
    const int*   toks_mem = (const int*)  d_in[1];
    const float* emb      = (const float*)d_in[2];
    const float* w1       = (const float*)d_in[3];
    const float* b1       = (const float*)d_in[4];
    const float* w2       = (const float*)d_in[5];
    const float* b2       = (const float*)d_in[6];
    const int n_toks = in_sizes[0];

    gemv_kernel<<<MSL * NSLAB, 256>>>(toks_in, n_toks, toks_mem, emb, w1);
    reduce_kernel<<<128, 256>>>(b1);
    final_kernel<<<1, 256>>>(toks_in, n_toks, toks_mem, w2, b2, (float*)d_out);
}